// round 14
// baseline (speedup 1.0000x reference)
#include <cuda_runtime.h>
#include <cuda_bf16.h>
#include <cstdint>

// Elementwise hard clip: out[i] = clamp(x[i], -0.5f, 0.5f)
// N = 67,108,864 fp32. 4096 CTAs x 256 threads, 64KB contiguous tile per CTA,
// one straight-line batch per CTA: 8 x 256-bit NON-COHERENT streaming loads
// (read-only datapath), clip, 8 x 256-bit WRITE-THROUGH stores.

#define CLIP_LO (-0.5f)
#define CLIP_HI (0.5f)
#define BATCH 8   // 8 x 32B = 256B per thread

struct f8 { float v[8]; };

__device__ __forceinline__ f8 ld256nc(const float* p) {
    f8 r;
    asm volatile(
        "ld.global.nc.cs.v8.f32 {%0,%1,%2,%3,%4,%5,%6,%7}, [%8];"
        : "=f"(r.v[0]), "=f"(r.v[1]), "=f"(r.v[2]), "=f"(r.v[3]),
          "=f"(r.v[4]), "=f"(r.v[5]), "=f"(r.v[6]), "=f"(r.v[7])
        : "l"(p));
    return r;
}

__device__ __forceinline__ void st256wt(float* p, const f8& r) {
    asm volatile(
        "st.global.wt.v8.f32 [%0], {%1,%2,%3,%4,%5,%6,%7,%8};"
        :: "l"(p),
           "f"(r.v[0]), "f"(r.v[1]), "f"(r.v[2]), "f"(r.v[3]),
           "f"(r.v[4]), "f"(r.v[5]), "f"(r.v[6]), "f"(r.v[7])
        : "memory");
}

__device__ __forceinline__ void clip8(f8& a) {
#pragma unroll
    for (int k = 0; k < 8; k++)
        a.v[k] = fminf(fmaxf(a.v[k], CLIP_LO), CLIP_HI);
}

// Each CTA owns a contiguous tile [start, start+chunk) in float8 (32B) units.
// For this problem chunk == BATCH*blockDim: one straight-line iteration.
__global__ __launch_bounds__(256) void clip_kernel_ncwt(
    const float* __restrict__ in, float* __restrict__ out,
    int n8, int chunk)
{
    const int bdim = blockDim.x;
    int start = blockIdx.x * chunk;
    int end = start + chunk;
    if (end > n8) end = n8;

    int i = start + threadIdx.x;
    const int step = bdim * BATCH;

    for (; i + (BATCH - 1) * bdim < end; i += step) {
        f8 v[BATCH];
#pragma unroll
        for (int j = 0; j < BATCH; j++)
            v[j] = ld256nc(in + (size_t)(i + j * bdim) * 8);
#pragma unroll
        for (int j = 0; j < BATCH; j++)
            clip8(v[j]);
#pragma unroll
        for (int j = 0; j < BATCH; j++)
            st256wt(out + (size_t)(i + j * bdim) * 8, v[j]);
    }
    // Remainder within the tile (sub-BATCH iterations; not hit for this N).
    for (; i < end; i += bdim) {
        f8 a = ld256nc(in + (size_t)i * 8);
        clip8(a);
        st256wt(out + (size_t)i * 8, a);
    }
}

// Scalar tail for N not divisible by 8 (not hit for this problem's N).
__global__ void clip_kernel_tail(
    const float* __restrict__ in, float* __restrict__ out, int start, int n)
{
    int i = start + blockIdx.x * blockDim.x + threadIdx.x;
    if (i < n) {
        out[i] = fminf(fmaxf(__ldcs(in + i), CLIP_LO), CLIP_HI);
    }
}

extern "C" void kernel_launch(void* const* d_in, const int* in_sizes, int n_in,
                              void* d_out, int out_size)
{
    const float* x = (const float*)d_in[0];
    float* out = (float*)d_out;
    int n = in_sizes[0];

    int n8 = n / 8;
    const int threads = 256;

    // 4096 CTAs: for n8 = 2^23, chunk = 2048 float8 = 64KB contiguous per CTA
    // = exactly one BATCH=8 straight-line iteration.
    int blocks = 4096;
    int chunk = (n8 + blocks - 1) / blocks;
    chunk = ((chunk + threads - 1) / threads) * threads;
    blocks = (n8 + chunk - 1) / chunk;
    if (blocks < 1) { blocks = 1; chunk = n8 > 0 ? n8 : 1; }

    clip_kernel_ncwt<<<blocks, threads>>>(x, out, n8, chunk);

    int tail_start = n8 * 8;
    int tail = n - tail_start;
    if (tail > 0) {
        clip_kernel_tail<<<(tail + 255) / 256, 256>>>(x, out, tail_start, n);
    }
}

// round 15
// speedup vs baseline: 1.0254x; 1.0254x over previous
#include <cuda_runtime.h>
#include <cuda_bf16.h>
#include <cstdint>

// Elementwise hard clip: out[i] = clamp(x[i], -0.5f, 0.5f)
// N = 67,108,864 fp32. FINAL (measured best across 14 rounds, R13 config):
// 4096 CTAs x 256 threads, 64KB contiguous tile per CTA, one straight-line
// batch per CTA: 8 x 256-bit streaming (.cs) loads = 64KB read burst, clip,
// 8 x 256-bit write-through (.wt) stores = 64KB write burst (no L2
// dirty-line deferral; output never re-read).
// Measured: 73.5us kernel, 6553 GB/s HBM (82.7% DRAM-active) = 7.3 TB/s
// effective motion, ~91% of spec for a 50/50 R/W stream.
// NOTE: keep .cs (not .nc) loads — .nc makes ptxas serialize the batch
// (regs 86 -> 32) and destroys the read burst (R14 regression).

#define CLIP_LO (-0.5f)
#define CLIP_HI (0.5f)
#define BATCH 8   // 8 x 32B = 256B per thread

struct f8 { float v[8]; };

__device__ __forceinline__ f8 ld256cs(const float* p) {
    f8 r;
    asm volatile(
        "ld.global.cs.v8.f32 {%0,%1,%2,%3,%4,%5,%6,%7}, [%8];"
        : "=f"(r.v[0]), "=f"(r.v[1]), "=f"(r.v[2]), "=f"(r.v[3]),
          "=f"(r.v[4]), "=f"(r.v[5]), "=f"(r.v[6]), "=f"(r.v[7])
        : "l"(p));
    return r;
}

__device__ __forceinline__ void st256wt(float* p, const f8& r) {
    asm volatile(
        "st.global.wt.v8.f32 [%0], {%1,%2,%3,%4,%5,%6,%7,%8};"
        :: "l"(p),
           "f"(r.v[0]), "f"(r.v[1]), "f"(r.v[2]), "f"(r.v[3]),
           "f"(r.v[4]), "f"(r.v[5]), "f"(r.v[6]), "f"(r.v[7])
        : "memory");
}

__device__ __forceinline__ void clip8(f8& a) {
#pragma unroll
    for (int k = 0; k < 8; k++)
        a.v[k] = fminf(fmaxf(a.v[k], CLIP_LO), CLIP_HI);
}

// Each CTA owns a contiguous tile [start, start+chunk) in float8 (32B) units.
// For this problem chunk == BATCH*blockDim: one straight-line iteration.
__global__ __launch_bounds__(256) void clip_kernel_wt(
    const float* __restrict__ in, float* __restrict__ out,
    int n8, int chunk)
{
    const int bdim = blockDim.x;
    int start = blockIdx.x * chunk;
    int end = start + chunk;
    if (end > n8) end = n8;

    int i = start + threadIdx.x;
    const int step = bdim * BATCH;

    for (; i + (BATCH - 1) * bdim < end; i += step) {
        f8 v[BATCH];
#pragma unroll
        for (int j = 0; j < BATCH; j++)
            v[j] = ld256cs(in + (size_t)(i + j * bdim) * 8);
#pragma unroll
        for (int j = 0; j < BATCH; j++)
            clip8(v[j]);
#pragma unroll
        for (int j = 0; j < BATCH; j++)
            st256wt(out + (size_t)(i + j * bdim) * 8, v[j]);
    }
    // Remainder within the tile (sub-BATCH iterations; not hit for this N).
    for (; i < end; i += bdim) {
        f8 a = ld256cs(in + (size_t)i * 8);
        clip8(a);
        st256wt(out + (size_t)i * 8, a);
    }
}

// Scalar tail for N not divisible by 8 (not hit for this problem's N).
__global__ void clip_kernel_tail(
    const float* __restrict__ in, float* __restrict__ out, int start, int n)
{
    int i = start + blockIdx.x * blockDim.x + threadIdx.x;
    if (i < n) {
        out[i] = fminf(fmaxf(__ldcs(in + i), CLIP_LO), CLIP_HI);
    }
}

extern "C" void kernel_launch(void* const* d_in, const int* in_sizes, int n_in,
                              void* d_out, int out_size)
{
    const float* x = (const float*)d_in[0];
    float* out = (float*)d_out;
    int n = in_sizes[0];

    int n8 = n / 8;
    const int threads = 256;

    // 4096 CTAs: for n8 = 2^23, chunk = 2048 float8 = 64KB contiguous per CTA
    // = exactly one BATCH=8 straight-line iteration.
    int blocks = 4096;
    int chunk = (n8 + blocks - 1) / blocks;
    chunk = ((chunk + threads - 1) / threads) * threads;
    blocks = (n8 + chunk - 1) / chunk;
    if (blocks < 1) { blocks = 1; chunk = n8 > 0 ? n8 : 1; }

    clip_kernel_wt<<<blocks, threads>>>(x, out, n8, chunk);

    int tail_start = n8 * 8;
    int tail = n - tail_start;
    if (tail > 0) {
        clip_kernel_tail<<<(tail + 255) / 256, 256>>>(x, out, tail_start, n);
    }
}